// round 1
// baseline (speedup 1.0000x reference)
#include <cuda_runtime.h>
#include <math_constants.h>

#define B_      8
#define H_      32
#define DK_     128
#define DM_     4096
#define MAXLEN_ 4096

// Scratch (no allocation allowed in kernel_launch)
__device__ float g_q[B_ * DM_];
__device__ float g_k[B_ * DM_];
__device__ float g_v[B_ * DM_];
__device__ float g_attn[B_ * DM_];

// ---------------------------------------------------------------------------
// GEMV: y[b][j] = sum_i x[b][i] * W[j][i] + bias[j]  for b in [0,8), j in [0,4096)
// Block: 256 threads = 8 warps; each warp owns 4 rows of W; lanes stride columns
// by float4. x (all 8 batches, 128KB) lives in dynamic smem.
// ---------------------------------------------------------------------------
__device__ __forceinline__ void proj_body(const float* __restrict__ x,
                                          const float* __restrict__ W,
                                          const float* __restrict__ bias,
                                          float* __restrict__ y,
                                          float* xs) {
    const int tid = threadIdx.x;
    // stage x into smem (8 * 4096 floats)
    const float4* xg  = (const float4*)x;
    float4*       xs4 = (float4*)xs;
    #pragma unroll 4
    for (int i = tid; i < B_ * DM_ / 4; i += 256) xs4[i] = xg[i];
    __syncthreads();

    const int warp = tid >> 5;
    const int lane = tid & 31;
    const int row0 = blockIdx.x * 32 + warp * 4;

    float acc[4][B_];
    #pragma unroll
    for (int r = 0; r < 4; r++)
        #pragma unroll
        for (int b = 0; b < B_; b++) acc[r][b] = 0.f;

    const float4* w0p = (const float4*)(W + (size_t)(row0 + 0) * DM_);
    const float4* w1p = (const float4*)(W + (size_t)(row0 + 1) * DM_);
    const float4* w2p = (const float4*)(W + (size_t)(row0 + 2) * DM_);
    const float4* w3p = (const float4*)(W + (size_t)(row0 + 3) * DM_);

    #pragma unroll 2
    for (int it = 0; it < DM_ / 128; ++it) {
        const int c4 = it * 32 + lane;
        const float4 w0 = w0p[c4];
        const float4 w1 = w1p[c4];
        const float4 w2 = w2p[c4];
        const float4 w3 = w3p[c4];
        #pragma unroll
        for (int b = 0; b < B_; b++) {
            const float4 xb = xs4[b * (DM_ / 4) + c4];
            acc[0][b] += w0.x * xb.x + w0.y * xb.y + w0.z * xb.z + w0.w * xb.w;
            acc[1][b] += w1.x * xb.x + w1.y * xb.y + w1.z * xb.z + w1.w * xb.w;
            acc[2][b] += w2.x * xb.x + w2.y * xb.y + w2.z * xb.z + w2.w * xb.w;
            acc[3][b] += w3.x * xb.x + w3.y * xb.y + w3.z * xb.z + w3.w * xb.w;
        }
    }

    // warp reduce each (row, batch) and write
    #pragma unroll
    for (int r = 0; r < 4; r++) {
        const float bb = bias[row0 + r];
        #pragma unroll
        for (int b = 0; b < B_; b++) {
            float v = acc[r][b];
            v += __shfl_xor_sync(0xffffffffu, v, 16);
            v += __shfl_xor_sync(0xffffffffu, v, 8);
            v += __shfl_xor_sync(0xffffffffu, v, 4);
            v += __shfl_xor_sync(0xffffffffu, v, 2);
            v += __shfl_xor_sync(0xffffffffu, v, 1);
            if (lane == 0) y[b * DM_ + row0 + r] = v + bb;
        }
    }
}

__global__ void __launch_bounds__(256)
proj_qkv_kernel(const float* __restrict__ q_in, const float* __restrict__ k_in,
                const float* __restrict__ v_in,
                const float* __restrict__ Wq, const float* __restrict__ bq,
                const float* __restrict__ Wk, const float* __restrict__ bk,
                const float* __restrict__ Wv, const float* __restrict__ bv) {
    extern __shared__ float xs[];
    const float* x; const float* W; const float* bias; float* y;
    if (blockIdx.y == 0)      { x = q_in; W = Wq; bias = bq; y = g_q; }
    else if (blockIdx.y == 1) { x = k_in; W = Wk; bias = bk; y = g_k; }
    else                      { x = v_in; W = Wv; bias = bv; y = g_v; }
    proj_body(x, W, bias, y, xs);
}

__global__ void __launch_bounds__(256)
proj_out_kernel(const float* __restrict__ Wo, const float* __restrict__ bo,
                float* __restrict__ out) {
    extern __shared__ float xs[];
    proj_body(g_attn, Wo, bo, out, xs);
}

// ---------------------------------------------------------------------------
// Attention: one block per (b,h). 8 warps; warp w handles keys w, w+8, ...
// Warp-per-key: lane l holds q[4l..4l+3]; online softmax per warp, smem combine.
// Key index (L-1) comes from the freshly projected k_new/v_new scratch.
// ---------------------------------------------------------------------------
__global__ void __launch_bounds__(256)
attn_kernel(const float* __restrict__ kc, const float* __restrict__ vc,
            const int* __restrict__ cache_len_p) {
    const int bh = blockIdx.x;
    const int b  = bh >> 5;      // /H_
    const int h  = bh & 31;
    const int L  = cache_len_p[0] + 1;
    const int Lm1 = L - 1;

    const int tid  = threadIdx.x;
    const int warp = tid >> 5;
    const int lane = tid & 31;

    const float scale = 0.08838834764831843f; // 1/sqrt(128)
    float4 q4 = ((const float4*)(g_q + b * DM_ + h * DK_))[lane];
    q4.x *= scale; q4.y *= scale; q4.z *= scale; q4.w *= scale;

    const float4* kb   = (const float4*)(kc + (((size_t)b * H_ + h) * (size_t)MAXLEN_) * DK_);
    const float4* vb   = (const float4*)(vc + (((size_t)b * H_ + h) * (size_t)MAXLEN_) * DK_);
    const float4* knew = (const float4*)(g_k + b * DM_ + h * DK_);
    const float4* vnew = (const float4*)(g_v + b * DM_ + h * DK_);

    float m = -CUDART_INF_F;
    float lsum = 0.f;
    float4 a = make_float4(0.f, 0.f, 0.f, 0.f);

    int key = warp;
    // 2-key unrolled main loop (MLP = 4 loads in flight per warp)
    for (; key + 8 < L; key += 16) {
        const int k1 = key, k2 = key + 8;
        const float4* kr1 = (k1 == Lm1) ? knew : (kb + (size_t)k1 * 32);
        const float4* vr1 = (k1 == Lm1) ? vnew : (vb + (size_t)k1 * 32);
        const float4* kr2 = (k2 == Lm1) ? knew : (kb + (size_t)k2 * 32);
        const float4* vr2 = (k2 == Lm1) ? vnew : (vb + (size_t)k2 * 32);
        const float4 K1 = kr1[lane];
        const float4 K2 = kr2[lane];
        const float4 V1 = vr1[lane];
        const float4 V2 = vr2[lane];

        float s1 = q4.x * K1.x + q4.y * K1.y + q4.z * K1.z + q4.w * K1.w;
        float s2 = q4.x * K2.x + q4.y * K2.y + q4.z * K2.z + q4.w * K2.w;
        #pragma unroll
        for (int o = 16; o > 0; o >>= 1) {
            s1 += __shfl_xor_sync(0xffffffffu, s1, o);
            s2 += __shfl_xor_sync(0xffffffffu, s2, o);
        }

        const float mn   = fmaxf(m, fmaxf(s1, s2));
        const float corr = __expf(m - mn);
        const float p1   = __expf(s1 - mn);
        const float p2   = __expf(s2 - mn);
        lsum = lsum * corr + p1 + p2;
        a.x = a.x * corr + p1 * V1.x + p2 * V2.x;
        a.y = a.y * corr + p1 * V1.y + p2 * V2.y;
        a.z = a.z * corr + p1 * V1.z + p2 * V2.z;
        a.w = a.w * corr + p1 * V1.w + p2 * V2.w;
        m = mn;
    }
    if (key < L) {
        const float4* kr = (key == Lm1) ? knew : (kb + (size_t)key * 32);
        const float4* vr = (key == Lm1) ? vnew : (vb + (size_t)key * 32);
        const float4 K1 = kr[lane];
        const float4 V1 = vr[lane];
        float s1 = q4.x * K1.x + q4.y * K1.y + q4.z * K1.z + q4.w * K1.w;
        #pragma unroll
        for (int o = 16; o > 0; o >>= 1) s1 += __shfl_xor_sync(0xffffffffu, s1, o);
        const float mn   = fmaxf(m, s1);
        const float corr = __expf(m - mn);
        const float p1   = __expf(s1 - mn);
        lsum = lsum * corr + p1;
        a.x = a.x * corr + p1 * V1.x;
        a.y = a.y * corr + p1 * V1.y;
        a.z = a.z * corr + p1 * V1.z;
        a.w = a.w * corr + p1 * V1.w;
        m = mn;
    }

    // cross-warp combine
    __shared__ float  sm_m[8];
    __shared__ float  sm_l[8];
    __shared__ float4 sm_a[8][32];
    if (lane == 0) { sm_m[warp] = m; sm_l[warp] = lsum; }
    sm_a[warp][lane] = a;
    __syncthreads();

    if (tid < 128) {
        float M = sm_m[0];
        #pragma unroll
        for (int w = 1; w < 8; w++) M = fmaxf(M, sm_m[w]);
        float Ls = 0.f, o = 0.f;
        const float* sa = (const float*)sm_a;  // [8][128]
        #pragma unroll
        for (int w = 0; w < 8; w++) {
            const float e = __expf(sm_m[w] - M);
            Ls += e * sm_l[w];
            o  += e * sa[w * 128 + tid];
        }
        g_attn[b * DM_ + h * DK_ + tid] = o / Ls;
    }
}

// ---------------------------------------------------------------------------
extern "C" void kernel_launch(void* const* d_in, const int* in_sizes, int n_in,
                              void* d_out, int out_size) {
    const float* query = (const float*)d_in[0];
    const float* keyv  = (const float*)d_in[1];
    const float* value = (const float*)d_in[2];
    const float* kc    = (const float*)d_in[3];
    const float* vc    = (const float*)d_in[4];
    const float* Wq    = (const float*)d_in[5];
    const float* bq    = (const float*)d_in[6];
    const float* Wk    = (const float*)d_in[7];
    const float* bk    = (const float*)d_in[8];
    const float* Wv    = (const float*)d_in[9];
    const float* bv    = (const float*)d_in[10];
    const float* Wo    = (const float*)d_in[11];
    const float* bo    = (const float*)d_in[12];
    const int*   clp   = (const int*)d_in[13];  // 4095 in low 32 bits either way

    const int smem = B_ * DM_ * sizeof(float);  // 128 KB
    cudaFuncSetAttribute(proj_qkv_kernel, cudaFuncAttributeMaxDynamicSharedMemorySize, smem);
    cudaFuncSetAttribute(proj_out_kernel, cudaFuncAttributeMaxDynamicSharedMemorySize, smem);

    dim3 gqkv(DM_ / 32, 3);
    proj_qkv_kernel<<<gqkv, 256, smem>>>(query, keyv, value, Wq, bq, Wk, bk, Wv, bv);
    attn_kernel<<<B_ * H_, 256>>>(kc, vc, clp);
    proj_out_kernel<<<DM_ / 32, 256, smem>>>(Wo, bo, (float*)d_out);
}

// round 2
// speedup vs baseline: 1.6999x; 1.6999x over previous
#include <cuda_runtime.h>
#include <math_constants.h>

#define B_      8
#define H_      32
#define DK_     128
#define DM_     4096
#define MAXLEN_ 4096
#define SPLIT_  4

// Scratch (no allocation allowed in kernel_launch)
__device__ float g_q[B_ * DM_];
__device__ float g_k[B_ * DM_];
__device__ float g_v[B_ * DM_];
__device__ float g_attn[B_ * DM_];
__device__ float g_pm[B_ * H_ * SPLIT_];
__device__ float g_pl[B_ * H_ * SPLIT_];
__device__ float g_pa[B_ * H_ * SPLIT_ * DK_];

__device__ __forceinline__ float dot4(float4 a, float4 b) {
    return a.x * b.x + a.y * b.y + a.z * b.z + a.w * b.w;
}

// ---------------------------------------------------------------------------
// GEMV: y[b][j] = sum_i x[b][i] * W[j][i] + bias[j], b in [0,8), j in [0,4096)
// No smem: x (128KB total) stays L1-resident (W streamed with __ldcs so it
// doesn't evict x). 256 threads = 8 warps, each warp 4 rows, unroll-2 columns
// -> 8 W float4 loads in flight per warp. 2 CTAs/SM.
// ---------------------------------------------------------------------------
__device__ __forceinline__ void proj_body(const float4* __restrict__ x4,
                                          const float* __restrict__ W,
                                          const float* __restrict__ bias,
                                          float* __restrict__ y) {
    const int tid  = threadIdx.x;
    const int warp = tid >> 5;
    const int lane = tid & 31;
    const int row0 = blockIdx.x * 32 + warp * 4;

    float acc[4][B_];
    #pragma unroll
    for (int r = 0; r < 4; r++)
        #pragma unroll
        for (int b = 0; b < B_; b++) acc[r][b] = 0.f;

    const float4* w0p = (const float4*)(W + (size_t)(row0 + 0) * DM_);
    const float4* w1p = (const float4*)(W + (size_t)(row0 + 1) * DM_);
    const float4* w2p = (const float4*)(W + (size_t)(row0 + 2) * DM_);
    const float4* w3p = (const float4*)(W + (size_t)(row0 + 3) * DM_);

    for (int it = 0; it < DM_ / 256; ++it) {
        const int c0 = it * 64 + lane;
        const int c1 = c0 + 32;
        // 8 streaming loads issued together (evict-first: keep x in L1)
        const float4 wa0 = __ldcs(w0p + c0), wb0 = __ldcs(w0p + c1);
        const float4 wa1 = __ldcs(w1p + c0), wb1 = __ldcs(w1p + c1);
        const float4 wa2 = __ldcs(w2p + c0), wb2 = __ldcs(w2p + c1);
        const float4 wa3 = __ldcs(w3p + c0), wb3 = __ldcs(w3p + c1);
        #pragma unroll
        for (int b = 0; b < B_; b++) {
            const float4 xa = __ldg(x4 + b * (DM_ / 4) + c0);
            acc[0][b] += dot4(wa0, xa);
            acc[1][b] += dot4(wa1, xa);
            acc[2][b] += dot4(wa2, xa);
            acc[3][b] += dot4(wa3, xa);
            const float4 xb = __ldg(x4 + b * (DM_ / 4) + c1);
            acc[0][b] += dot4(wb0, xb);
            acc[1][b] += dot4(wb1, xb);
            acc[2][b] += dot4(wb2, xb);
            acc[3][b] += dot4(wb3, xb);
        }
    }

    #pragma unroll
    for (int r = 0; r < 4; r++) {
        const float bb = bias[row0 + r];
        #pragma unroll
        for (int b = 0; b < B_; b++) {
            float v = acc[r][b];
            v += __shfl_xor_sync(0xffffffffu, v, 16);
            v += __shfl_xor_sync(0xffffffffu, v, 8);
            v += __shfl_xor_sync(0xffffffffu, v, 4);
            v += __shfl_xor_sync(0xffffffffu, v, 2);
            v += __shfl_xor_sync(0xffffffffu, v, 1);
            if (lane == 0) y[b * DM_ + row0 + r] = v + bb;
        }
    }
}

__global__ void __launch_bounds__(256, 2)
proj_qkv_kernel(const float* __restrict__ q_in, const float* __restrict__ k_in,
                const float* __restrict__ v_in,
                const float* __restrict__ Wq, const float* __restrict__ bq,
                const float* __restrict__ Wk, const float* __restrict__ bk,
                const float* __restrict__ Wv, const float* __restrict__ bv) {
    const float* x; const float* W; const float* bias; float* y;
    if (blockIdx.y == 0)      { x = q_in; W = Wq; bias = bq; y = g_q; }
    else if (blockIdx.y == 1) { x = k_in; W = Wk; bias = bk; y = g_k; }
    else                      { x = v_in; W = Wv; bias = bv; y = g_v; }
    proj_body((const float4*)x, W, bias, y);
}

__global__ void __launch_bounds__(256, 2)
proj_out_kernel(const float* __restrict__ Wo, const float* __restrict__ bo,
                float* __restrict__ out) {
    proj_body((const float4*)g_attn, Wo, bo, out);
}

// ---------------------------------------------------------------------------
// Attention, split-K: grid (256, SPLIT_). Block (bh, s) handles keys
// [s*chunk, min((s+1)*chunk, L)). 8 warps; warp w owns keys start+w, step 8,
// 4-key unrolled (8 float4 loads in flight per warp). Online softmax per warp,
// smem combine per block, partial (m, l, acc) to global scratch.
// ---------------------------------------------------------------------------
__global__ void __launch_bounds__(256)
attn_kernel(const float* __restrict__ kc, const float* __restrict__ vc,
            const int* __restrict__ cache_len_p) {
    const int bh = blockIdx.x;
    const int b  = bh >> 5;
    const int h  = bh & 31;
    const int s  = blockIdx.y;
    const int L  = cache_len_p[0] + 1;
    const int Lm1 = L - 1;
    const int chunk = (L + SPLIT_ - 1) / SPLIT_;
    const int start = s * chunk;
    const int end   = min(start + chunk, L);

    const int tid  = threadIdx.x;
    const int warp = tid >> 5;
    const int lane = tid & 31;

    const float scale = 0.08838834764831843f; // 1/sqrt(128)
    float4 q4 = ((const float4*)(g_q + b * DM_ + h * DK_))[lane];
    q4.x *= scale; q4.y *= scale; q4.z *= scale; q4.w *= scale;

    const float4* kb   = (const float4*)(kc + (((size_t)b * H_ + h) * (size_t)MAXLEN_) * DK_);
    const float4* vb   = (const float4*)(vc + (((size_t)b * H_ + h) * (size_t)MAXLEN_) * DK_);
    const float4* knew = (const float4*)(g_k + b * DM_ + h * DK_);
    const float4* vnew = (const float4*)(g_v + b * DM_ + h * DK_);

    float m = -CUDART_INF_F;
    float lsum = 0.f;
    float4 a = make_float4(0.f, 0.f, 0.f, 0.f);

    int key = start + warp;
    // 4-key unrolled main loop (8 float4 loads in flight per warp)
    for (; key + 24 < end; key += 32) {
        const int k1 = key, k2 = key + 8, k3 = key + 16, k4 = key + 24;
        const float4* kr1 = (k1 == Lm1) ? knew : (kb + (size_t)k1 * 32);
        const float4* kr2 = (k2 == Lm1) ? knew : (kb + (size_t)k2 * 32);
        const float4* kr3 = (k3 == Lm1) ? knew : (kb + (size_t)k3 * 32);
        const float4* kr4 = (k4 == Lm1) ? knew : (kb + (size_t)k4 * 32);
        const float4* vr1 = (k1 == Lm1) ? vnew : (vb + (size_t)k1 * 32);
        const float4* vr2 = (k2 == Lm1) ? vnew : (vb + (size_t)k2 * 32);
        const float4* vr3 = (k3 == Lm1) ? vnew : (vb + (size_t)k3 * 32);
        const float4* vr4 = (k4 == Lm1) ? vnew : (vb + (size_t)k4 * 32);
        const float4 K1 = kr1[lane];
        const float4 K2 = kr2[lane];
        const float4 K3 = kr3[lane];
        const float4 K4 = kr4[lane];
        const float4 V1 = vr1[lane];
        const float4 V2 = vr2[lane];
        const float4 V3 = vr3[lane];
        const float4 V4 = vr4[lane];

        float s1 = dot4(q4, K1);
        float s2 = dot4(q4, K2);
        float s3 = dot4(q4, K3);
        float s4 = dot4(q4, K4);
        #pragma unroll
        for (int o = 16; o > 0; o >>= 1) {
            s1 += __shfl_xor_sync(0xffffffffu, s1, o);
            s2 += __shfl_xor_sync(0xffffffffu, s2, o);
            s3 += __shfl_xor_sync(0xffffffffu, s3, o);
            s4 += __shfl_xor_sync(0xffffffffu, s4, o);
        }

        const float mn = fmaxf(fmaxf(m, fmaxf(s1, s2)), fmaxf(s3, s4));
        const float corr = __expf(m - mn);
        const float p1 = __expf(s1 - mn);
        const float p2 = __expf(s2 - mn);
        const float p3 = __expf(s3 - mn);
        const float p4 = __expf(s4 - mn);
        lsum = lsum * corr + (p1 + p2) + (p3 + p4);
        a.x = a.x * corr + p1 * V1.x + p2 * V2.x + p3 * V3.x + p4 * V4.x;
        a.y = a.y * corr + p1 * V1.y + p2 * V2.y + p3 * V3.y + p4 * V4.y;
        a.z = a.z * corr + p1 * V1.z + p2 * V2.z + p3 * V3.z + p4 * V4.z;
        a.w = a.w * corr + p1 * V1.w + p2 * V2.w + p3 * V3.w + p4 * V4.w;
        m = mn;
    }
    for (; key < end; key += 8) {
        const float4* kr = (key == Lm1) ? knew : (kb + (size_t)key * 32);
        const float4* vr = (key == Lm1) ? vnew : (vb + (size_t)key * 32);
        const float4 K1 = kr[lane];
        const float4 V1 = vr[lane];
        float s1 = dot4(q4, K1);
        #pragma unroll
        for (int o = 16; o > 0; o >>= 1) s1 += __shfl_xor_sync(0xffffffffu, s1, o);
        const float mn = fmaxf(m, s1);
        const float corr = __expf(m - mn);
        const float p1 = __expf(s1 - mn);
        lsum = lsum * corr + p1;
        a.x = a.x * corr + p1 * V1.x;
        a.y = a.y * corr + p1 * V1.y;
        a.z = a.z * corr + p1 * V1.z;
        a.w = a.w * corr + p1 * V1.w;
        m = mn;
    }

    // cross-warp combine -> unnormalized block partial
    __shared__ float  sm_m[8];
    __shared__ float  sm_l[8];
    __shared__ float4 sm_a[8][32];
    if (lane == 0) { sm_m[warp] = m; sm_l[warp] = lsum; }
    sm_a[warp][lane] = a;
    __syncthreads();

    if (tid < 128) {
        float M = sm_m[0];
        #pragma unroll
        for (int w = 1; w < 8; w++) M = fmaxf(M, sm_m[w]);
        float Ls = 0.f, o = 0.f;
        const float* sa = (const float*)sm_a;  // [8][128]
        #pragma unroll
        for (int w = 0; w < 8; w++) {
            const float e = __expf(sm_m[w] - M);
            Ls += e * sm_l[w];
            o  += e * sa[w * 128 + tid];
        }
        const int idx = bh * SPLIT_ + s;
        g_pa[idx * DK_ + tid] = o;
        if (tid == 0) { g_pm[idx] = M; g_pl[idx] = Ls; }
    }
}

__global__ void __launch_bounds__(128)
attn_reduce_kernel() {
    const int bh = blockIdx.x;
    const int d  = threadIdx.x;
    float M = -CUDART_INF_F;
    #pragma unroll
    for (int s = 0; s < SPLIT_; s++) M = fmaxf(M, g_pm[bh * SPLIT_ + s]);
    float Ls = 0.f, o = 0.f;
    #pragma unroll
    for (int s = 0; s < SPLIT_; s++) {
        const int idx = bh * SPLIT_ + s;
        const float e = __expf(g_pm[idx] - M);
        Ls += e * g_pl[idx];
        o  += e * g_pa[idx * DK_ + d];
    }
    g_attn[bh * DK_ + d] = o / Ls;
}

// ---------------------------------------------------------------------------
extern "C" void kernel_launch(void* const* d_in, const int* in_sizes, int n_in,
                              void* d_out, int out_size) {
    const float* query = (const float*)d_in[0];
    const float* keyv  = (const float*)d_in[1];
    const float* value = (const float*)d_in[2];
    const float* kc    = (const float*)d_in[3];
    const float* vc    = (const float*)d_in[4];
    const float* Wq    = (const float*)d_in[5];
    const float* bq    = (const float*)d_in[6];
    const float* Wk    = (const float*)d_in[7];
    const float* bk    = (const float*)d_in[8];
    const float* Wv    = (const float*)d_in[9];
    const float* bv    = (const float*)d_in[10];
    const float* Wo    = (const float*)d_in[11];
    const float* bo    = (const float*)d_in[12];
    const int*   clp   = (const int*)d_in[13];

    dim3 gqkv(DM_ / 32, 3);
    proj_qkv_kernel<<<gqkv, 256>>>(query, keyv, value, Wq, bq, Wk, bk, Wv, bv);
    dim3 gattn(B_ * H_, SPLIT_);
    attn_kernel<<<gattn, 256>>>(kc, vc, clp);
    attn_reduce_kernel<<<B_ * H_, 128>>>();
    proj_out_kernel<<<DM_ / 32, 256>>>(Wo, bo, (float*)d_out);
}

// round 3
// speedup vs baseline: 1.8416x; 1.0834x over previous
#include <cuda_runtime.h>
#include <math_constants.h>

#define B_      8
#define H_      32
#define DK_     128
#define DM_     4096
#define MAXLEN_ 4096
#define SPLIT_  4
#define KSPLIT_ 2

// Scratch (no allocation allowed in kernel_launch)
__device__ float g_qp[KSPLIT_][B_ * DM_];   // q projection partials
__device__ float g_kp[KSPLIT_][B_ * DM_];
__device__ float g_vp[KSPLIT_][B_ * DM_];
__device__ float g_op[KSPLIT_][B_ * DM_];   // output projection partials
__device__ float g_attn[B_ * DM_];
__device__ float g_pm[B_ * H_ * SPLIT_];
__device__ float g_pl[B_ * H_ * SPLIT_];
__device__ float g_pa[B_ * H_ * SPLIT_ * DK_];

__device__ __forceinline__ float dot4(float4 a, float4 b) {
    return a.x * b.x + a.y * b.y + a.z * b.z + a.w * b.w;
}
__device__ __forceinline__ float4 add4(float4 a, float4 b) {
    return make_float4(a.x + b.x, a.y + b.y, a.z + b.z, a.w + b.w);
}

// ---------------------------------------------------------------------------
// Split-K GEMV partial: yp[b][j] = sum_{i in slice} x[b][i] * W[j][i]
// Block: 256 thr = 8 warps x 4 rows = 32 rows; slice = 2048 columns.
// W streamed (__ldcs); x (64KB/slice) stays L1-resident across the block.
// ---------------------------------------------------------------------------
__device__ __forceinline__ void proj_body(const float4* __restrict__ x4,
                                          const float* __restrict__ W,
                                          float* __restrict__ yp,
                                          int kslice) {
    const int tid  = threadIdx.x;
    const int warp = tid >> 5;
    const int lane = tid & 31;
    const int row0 = blockIdx.x * 32 + warp * 4;
    const int cbase = kslice * (DM_ / KSPLIT_ / 4);   // float4 column base (512)

    float acc[4][B_];
    #pragma unroll
    for (int r = 0; r < 4; r++)
        #pragma unroll
        for (int b = 0; b < B_; b++) acc[r][b] = 0.f;

    const float4* w0p = (const float4*)(W + (size_t)(row0 + 0) * DM_);
    const float4* w1p = (const float4*)(W + (size_t)(row0 + 1) * DM_);
    const float4* w2p = (const float4*)(W + (size_t)(row0 + 2) * DM_);
    const float4* w3p = (const float4*)(W + (size_t)(row0 + 3) * DM_);

    for (int it = 0; it < DM_ / KSPLIT_ / 256; ++it) {   // 8 iters
        const int c0 = cbase + it * 64 + lane;
        const int c1 = c0 + 32;
        const float4 wa0 = __ldcs(w0p + c0), wb0 = __ldcs(w0p + c1);
        const float4 wa1 = __ldcs(w1p + c0), wb1 = __ldcs(w1p + c1);
        const float4 wa2 = __ldcs(w2p + c0), wb2 = __ldcs(w2p + c1);
        const float4 wa3 = __ldcs(w3p + c0), wb3 = __ldcs(w3p + c1);
        #pragma unroll
        for (int b = 0; b < B_; b++) {
            const float4 xa = __ldg(x4 + b * (DM_ / 4) + c0);
            acc[0][b] += dot4(wa0, xa);
            acc[1][b] += dot4(wa1, xa);
            acc[2][b] += dot4(wa2, xa);
            acc[3][b] += dot4(wa3, xa);
            const float4 xb = __ldg(x4 + b * (DM_ / 4) + c1);
            acc[0][b] += dot4(wb0, xb);
            acc[1][b] += dot4(wb1, xb);
            acc[2][b] += dot4(wb2, xb);
            acc[3][b] += dot4(wb3, xb);
        }
    }

    #pragma unroll
    for (int r = 0; r < 4; r++) {
        #pragma unroll
        for (int b = 0; b < B_; b++) {
            float v = acc[r][b];
            v += __shfl_xor_sync(0xffffffffu, v, 16);
            v += __shfl_xor_sync(0xffffffffu, v, 8);
            v += __shfl_xor_sync(0xffffffffu, v, 4);
            v += __shfl_xor_sync(0xffffffffu, v, 2);
            v += __shfl_xor_sync(0xffffffffu, v, 1);
            if (lane == 0) yp[b * DM_ + row0 + r] = v;
        }
    }
}

__global__ void __launch_bounds__(256, 2)
proj_qkv_kernel(const float* __restrict__ q_in, const float* __restrict__ k_in,
                const float* __restrict__ v_in,
                const float* __restrict__ Wq, const float* __restrict__ Wk,
                const float* __restrict__ Wv) {
    const int ks = blockIdx.y;
    const float* x; const float* W; float* y;
    if (blockIdx.z == 0)      { x = q_in; W = Wq; y = g_qp[ks]; }
    else if (blockIdx.z == 1) { x = k_in; W = Wk; y = g_kp[ks]; }
    else                      { x = v_in; W = Wv; y = g_vp[ks]; }
    proj_body((const float4*)x, W, y, ks);
}

__global__ void __launch_bounds__(256, 2)
proj_out_kernel(const float* __restrict__ Wo) {
    proj_body((const float4*)g_attn, Wo, g_op[blockIdx.y], blockIdx.y);
}

__global__ void __launch_bounds__(256)
final_add_kernel(const float* __restrict__ bo, float* __restrict__ out) {
    const int i = blockIdx.x * 256 + threadIdx.x;   // i in [0, B_*DM_)
    out[i] = g_op[0][i] + g_op[1][i] + bo[i & (DM_ - 1)];
}

// ---------------------------------------------------------------------------
// Attention, split-K over keys: grid (256, SPLIT_). 8 warps, warp-per-key
// stride 8, 4-key unroll. q / k_new / v_new are combined from the two
// projection partials + bias at block start (registers), then the new-key row
// is a register select inside the loop.
// ---------------------------------------------------------------------------
__global__ void __launch_bounds__(256)
attn_kernel(const float* __restrict__ kc, const float* __restrict__ vc,
            const float* __restrict__ bq, const float* __restrict__ bk,
            const float* __restrict__ bv, const int* __restrict__ cache_len_p) {
    const int bh = blockIdx.x;
    const int b  = bh >> 5;
    const int h  = bh & 31;
    const int s  = blockIdx.y;
    const int L  = cache_len_p[0] + 1;
    const int Lm1 = L - 1;
    const int chunk = (L + SPLIT_ - 1) / SPLIT_;
    const int start = s * chunk;
    const int end   = min(start + chunk, L);

    const int tid  = threadIdx.x;
    const int warp = tid >> 5;
    const int lane = tid & 31;

    const int voff = b * DM_ + h * DK_;   // float offset of this (b,h) vector
    const float scale = 0.08838834764831843f; // 1/sqrt(128)

    float4 q4 = add4(add4(((const float4*)(g_qp[0] + voff))[lane],
                          ((const float4*)(g_qp[1] + voff))[lane]),
                     ((const float4*)(bq + h * DK_))[lane]);
    q4.x *= scale; q4.y *= scale; q4.z *= scale; q4.w *= scale;

    const float4 Knew = add4(add4(((const float4*)(g_kp[0] + voff))[lane],
                                  ((const float4*)(g_kp[1] + voff))[lane]),
                             ((const float4*)(bk + h * DK_))[lane]);
    const float4 Vnew = add4(add4(((const float4*)(g_vp[0] + voff))[lane],
                                  ((const float4*)(g_vp[1] + voff))[lane]),
                             ((const float4*)(bv + h * DK_))[lane]);

    const float4* kb = (const float4*)(kc + (((size_t)b * H_ + h) * (size_t)MAXLEN_) * DK_);
    const float4* vb = (const float4*)(vc + (((size_t)b * H_ + h) * (size_t)MAXLEN_) * DK_);

    float m = -CUDART_INF_F;
    float lsum = 0.f;
    float4 a = make_float4(0.f, 0.f, 0.f, 0.f);

    int key = start + warp;
    for (; key + 24 < end; key += 32) {
        const int k1 = key, k2 = key + 8, k3 = key + 16, k4 = key + 24;
        float4 K1 = __ldcs(kb + (size_t)k1 * 32 + lane);
        float4 K2 = __ldcs(kb + (size_t)k2 * 32 + lane);
        float4 K3 = __ldcs(kb + (size_t)k3 * 32 + lane);
        float4 K4 = __ldcs(kb + (size_t)k4 * 32 + lane);
        float4 V1 = __ldcs(vb + (size_t)k1 * 32 + lane);
        float4 V2 = __ldcs(vb + (size_t)k2 * 32 + lane);
        float4 V3 = __ldcs(vb + (size_t)k3 * 32 + lane);
        float4 V4 = __ldcs(vb + (size_t)k4 * 32 + lane);
        if (k1 == Lm1) { K1 = Knew; V1 = Vnew; }
        if (k2 == Lm1) { K2 = Knew; V2 = Vnew; }
        if (k3 == Lm1) { K3 = Knew; V3 = Vnew; }
        if (k4 == Lm1) { K4 = Knew; V4 = Vnew; }

        float s1 = dot4(q4, K1);
        float s2 = dot4(q4, K2);
        float s3 = dot4(q4, K3);
        float s4 = dot4(q4, K4);
        #pragma unroll
        for (int o = 16; o > 0; o >>= 1) {
            s1 += __shfl_xor_sync(0xffffffffu, s1, o);
            s2 += __shfl_xor_sync(0xffffffffu, s2, o);
            s3 += __shfl_xor_sync(0xffffffffu, s3, o);
            s4 += __shfl_xor_sync(0xffffffffu, s4, o);
        }

        const float mn = fmaxf(fmaxf(m, fmaxf(s1, s2)), fmaxf(s3, s4));
        const float corr = __expf(m - mn);
        const float p1 = __expf(s1 - mn);
        const float p2 = __expf(s2 - mn);
        const float p3 = __expf(s3 - mn);
        const float p4 = __expf(s4 - mn);
        lsum = lsum * corr + (p1 + p2) + (p3 + p4);
        a.x = a.x * corr + p1 * V1.x + p2 * V2.x + p3 * V3.x + p4 * V4.x;
        a.y = a.y * corr + p1 * V1.y + p2 * V2.y + p3 * V3.y + p4 * V4.y;
        a.z = a.z * corr + p1 * V1.z + p2 * V2.z + p3 * V3.z + p4 * V4.z;
        a.w = a.w * corr + p1 * V1.w + p2 * V2.w + p3 * V3.w + p4 * V4.w;
        m = mn;
    }
    for (; key < end; key += 8) {
        float4 K1 = __ldcs(kb + (size_t)key * 32 + lane);
        float4 V1 = __ldcs(vb + (size_t)key * 32 + lane);
        if (key == Lm1) { K1 = Knew; V1 = Vnew; }
        float s1 = dot4(q4, K1);
        #pragma unroll
        for (int o = 16; o > 0; o >>= 1) s1 += __shfl_xor_sync(0xffffffffu, s1, o);
        const float mn = fmaxf(m, s1);
        const float corr = __expf(m - mn);
        const float p1 = __expf(s1 - mn);
        lsum = lsum * corr + p1;
        a.x = a.x * corr + p1 * V1.x;
        a.y = a.y * corr + p1 * V1.y;
        a.z = a.z * corr + p1 * V1.z;
        a.w = a.w * corr + p1 * V1.w;
        m = mn;
    }

    // cross-warp combine -> unnormalized block partial
    __shared__ float  sm_m[8];
    __shared__ float  sm_l[8];
    __shared__ float4 sm_a[8][32];
    if (lane == 0) { sm_m[warp] = m; sm_l[warp] = lsum; }
    sm_a[warp][lane] = a;
    __syncthreads();

    if (tid < 128) {
        float M = sm_m[0];
        #pragma unroll
        for (int w = 1; w < 8; w++) M = fmaxf(M, sm_m[w]);
        float Ls = 0.f, o = 0.f;
        const float* sa = (const float*)sm_a;  // [8][128]
        #pragma unroll
        for (int w = 0; w < 8; w++) {
            const float e = __expf(sm_m[w] - M);
            Ls += e * sm_l[w];
            o  += e * sa[w * 128 + tid];
        }
        const int idx = bh * SPLIT_ + s;
        g_pa[idx * DK_ + tid] = o;
        if (tid == 0) { g_pm[idx] = M; g_pl[idx] = Ls; }
    }
}

__global__ void __launch_bounds__(128)
attn_reduce_kernel() {
    const int bh = blockIdx.x;
    const int d  = threadIdx.x;
    float M = -CUDART_INF_F;
    #pragma unroll
    for (int s = 0; s < SPLIT_; s++) M = fmaxf(M, g_pm[bh * SPLIT_ + s]);
    float Ls = 0.f, o = 0.f;
    #pragma unroll
    for (int s = 0; s < SPLIT_; s++) {
        const int idx = bh * SPLIT_ + s;
        const float e = __expf(g_pm[idx] - M);
        Ls += e * g_pl[idx];
        o  += e * g_pa[idx * DK_ + d];
    }
    g_attn[bh * DK_ + d] = o / Ls;
}

// ---------------------------------------------------------------------------
extern "C" void kernel_launch(void* const* d_in, const int* in_sizes, int n_in,
                              void* d_out, int out_size) {
    const float* query = (const float*)d_in[0];
    const float* keyv  = (const float*)d_in[1];
    const float* value = (const float*)d_in[2];
    const float* kc    = (const float*)d_in[3];
    const float* vc    = (const float*)d_in[4];
    const float* Wq    = (const float*)d_in[5];
    const float* bq    = (const float*)d_in[6];
    const float* Wk    = (const float*)d_in[7];
    const float* bk    = (const float*)d_in[8];
    const float* Wv    = (const float*)d_in[9];
    const float* bv    = (const float*)d_in[10];
    const float* Wo    = (const float*)d_in[11];
    const float* bo    = (const float*)d_in[12];
    const int*   clp   = (const int*)d_in[13];

    dim3 gqkv(DM_ / 32, KSPLIT_, 3);
    proj_qkv_kernel<<<gqkv, 256>>>(query, keyv, value, Wq, Wk, Wv);
    dim3 gattn(B_ * H_, SPLIT_);
    attn_kernel<<<gattn, 256>>>(kc, vc, bq, bk, bv, clp);
    attn_reduce_kernel<<<B_ * H_, 128>>>();
    dim3 gout(DM_ / 32, KSPLIT_);
    proj_out_kernel<<<gout, 256>>>(Wo);
    final_add_kernel<<<B_ * DM_ / 256, 256>>>(bo, (float*)d_out);
}